// round 3
// baseline (speedup 1.0000x reference)
#include <cuda_runtime.h>
#include <math.h>

#define NTHREADS 128

__global__ __launch_bounds__(NTHREADS, 3)
void nerf_fused_kernel(const float* __restrict__ xyz,
                       const float* __restrict__ dirp,
                       const float* __restrict__ table,
                       const float* __restrict__ ws1,
                       const float* __restrict__ ws2,
                       const float* __restrict__ wr1,
                       const float* __restrict__ wr2,
                       const float* __restrict__ wr3,
                       float* __restrict__ out, int N)
{
    // Weights staged in shared; ws2 / wr3 transposed so dot products read
    // contiguous float4 rows.
    __shared__ __align__(16) float s_ws1[32 * 64];
    __shared__ __align__(16) float s_ws2t[17 * 64];
    __shared__ __align__(16) float s_wr1[32 * 64];
    __shared__ __align__(16) float s_wr2[64 * 64];
    __shared__ __align__(16) float s_wr3t[3 * 64];

    for (int t = threadIdx.x; t < 32 * 64; t += NTHREADS) s_ws1[t] = ws1[t];
    for (int t = threadIdx.x; t < 17 * 64; t += NTHREADS) {
        int j = t >> 6, i = t & 63;
        s_ws2t[t] = ws2[i * 17 + j];
    }
    for (int t = threadIdx.x; t < 32 * 64; t += NTHREADS) s_wr1[t] = wr1[t];
    for (int t = threadIdx.x; t < 64 * 64; t += NTHREADS) s_wr2[t] = wr2[t];
    for (int t = threadIdx.x; t < 3 * 64; t += NTHREADS) {
        int j = t >> 6, i = t & 63;
        s_wr3t[t] = wr3[i * 3 + j];
    }
    __syncthreads();

    int p = blockIdx.x * NTHREADS + threadIdx.x;
    if (p >= N) return;

    float x = xyz[3 * p + 0];
    float y = xyz[3 * p + 1];
    float z = xyz[3 * p + 2];

    // ------------------------------------------------------------------
    // Hash-grid encoding: 16 levels, F=2 features, trilinear interp
    // ------------------------------------------------------------------
    float enc[32];
    const int res_tab[16] = {16, 22, 30, 42, 58, 80, 111, 153,
                             212, 294, 406, 561, 775, 1072, 1481, 2047};

    #pragma unroll
    for (int l = 0; l < 16; l++) {
        const int res = res_tab[l];
        float px = x * (float)res, py = y * (float)res, pz = z * (float)res;
        float fx = floorf(px), fy = floorf(py), fz = floorf(pz);
        float wx = px - fx, wy = py - fy, wz = pz - fz;
        unsigned ix = (unsigned)fx, iy = (unsigned)fy, iz = (unsigned)fz;

        unsigned i0, i1, i2, i3, i4, i5, i6, i7;
        if (res <= 79) {  // dense level: (res+1)^3 <= 2^19
            unsigned s = (unsigned)(res + 1);
            unsigned ss = s * s;
            unsigned base = ix + iy * s + iz * ss;
            i0 = base;      i1 = base + 1;
            i2 = base + s;  i3 = base + s + 1;
            i4 = base + ss; i5 = i4 + 1;
            i6 = i4 + s;    i7 = i4 + s + 1;
        } else {            // hashed level
            const unsigned P1 = 2654435761u, P2 = 805459861u;
            const unsigned m = (1u << 19) - 1u;
            unsigned hx0 = ix, hx1 = ix + 1u;
            unsigned hy0 = iy * P1, hy1 = hy0 + P1;
            unsigned hz0 = iz * P2, hz1 = hz0 + P2;
            i0 = (hx0 ^ hy0 ^ hz0) & m; i1 = (hx1 ^ hy0 ^ hz0) & m;
            i2 = (hx0 ^ hy1 ^ hz0) & m; i3 = (hx1 ^ hy1 ^ hz0) & m;
            i4 = (hx0 ^ hy0 ^ hz1) & m; i5 = (hx1 ^ hy0 ^ hz1) & m;
            i6 = (hx0 ^ hy1 ^ hz1) & m; i7 = (hx1 ^ hy1 ^ hz1) & m;
        }

        const float2* tl = reinterpret_cast<const float2*>(table) + ((size_t)l << 19);
        float2 f0 = __ldg(tl + i0); float2 f1 = __ldg(tl + i1);
        float2 f2 = __ldg(tl + i2); float2 f3 = __ldg(tl + i3);
        float2 f4 = __ldg(tl + i4); float2 f5 = __ldg(tl + i5);
        float2 f6 = __ldg(tl + i6); float2 f7 = __ldg(tl + i7);

        // lerp chain (x, then y, then z) — identical to the weight-product sum
        float a0 = f0.x + wx * (f1.x - f0.x), b0 = f0.y + wx * (f1.y - f0.y);
        float a1 = f2.x + wx * (f3.x - f2.x), b1 = f2.y + wx * (f3.y - f2.y);
        float a2 = f4.x + wx * (f5.x - f4.x), b2 = f4.y + wx * (f5.y - f4.y);
        float a3 = f6.x + wx * (f7.x - f6.x), b3 = f6.y + wx * (f7.y - f6.y);
        float c0 = a0 + wy * (a1 - a0), d0 = b0 + wy * (b1 - b0);
        float c1 = a2 + wy * (a3 - a2), d1 = b2 + wy * (b3 - b2);
        enc[2 * l + 0] = c0 + wz * (c1 - c0);
        enc[2 * l + 1] = d0 + wz * (d1 - d0);
    }

    // ------------------------------------------------------------------
    // Sigma MLP: 32 -> 64 (relu) -> 17
    // ------------------------------------------------------------------
    float h[64];
    #pragma unroll
    for (int j = 0; j < 64; j++) h[j] = 0.0f;
    #pragma unroll
    for (int i = 0; i < 32; i++) {
        float e = enc[i];
        const float4* w4 = reinterpret_cast<const float4*>(s_ws1 + i * 64);
        #pragma unroll
        for (int j4 = 0; j4 < 16; j4++) {
            float4 w = w4[j4];
            h[4 * j4 + 0] = fmaf(e, w.x, h[4 * j4 + 0]);
            h[4 * j4 + 1] = fmaf(e, w.y, h[4 * j4 + 1]);
            h[4 * j4 + 2] = fmaf(e, w.z, h[4 * j4 + 2]);
            h[4 * j4 + 3] = fmaf(e, w.w, h[4 * j4 + 3]);
        }
    }
    #pragma unroll
    for (int j = 0; j < 64; j++) h[j] = fmaxf(h[j], 0.0f);

    float g[17];
    #pragma unroll
    for (int j = 0; j < 17; j++) {
        const float4* w4 = reinterpret_cast<const float4*>(s_ws2t + j * 64);
        float acc = 0.0f;
        #pragma unroll
        for (int i4 = 0; i4 < 16; i4++) {
            float4 w = w4[i4];
            acc = fmaf(h[4 * i4 + 0], w.x, acc);
            acc = fmaf(h[4 * i4 + 1], w.y, acc);
            acc = fmaf(h[4 * i4 + 2], w.z, acc);
            acc = fmaf(h[4 * i4 + 3], w.w, acc);
        }
        g[j] = acc;
    }

    // sigma output (relu), stored at [3N, 4N)
    out[3 * N + p] = fmaxf(g[0], 0.0f);

    // ------------------------------------------------------------------
    // SH degree-4 direction encoding on d = dir*2 - 1
    // ------------------------------------------------------------------
    float dx = dirp[3 * p + 0] * 2.0f - 1.0f;
    float dy = dirp[3 * p + 1] * 2.0f - 1.0f;
    float dz = dirp[3 * p + 2] * 2.0f - 1.0f;
    float x2 = dx * dx, y2 = dy * dy, z2 = dz * dz;
    float xy = dx * dy, yz = dy * dz, xz = dx * dz;

    float rin[32];
    rin[0]  = 0.28209479177387814f;
    rin[1]  = -0.48860251190291987f * dy;
    rin[2]  = 0.48860251190291987f * dz;
    rin[3]  = -0.48860251190291987f * dx;
    rin[4]  = 1.0925484305920792f * xy;
    rin[5]  = -1.0925484305920792f * yz;
    rin[6]  = 0.94617469575756f * z2 - 0.31539156525252f;
    rin[7]  = -1.0925484305920792f * xz;
    rin[8]  = 0.5462742152960396f * (x2 - y2);
    rin[9]  = 0.5900435899266435f * dy * (-3.0f * x2 + y2);
    rin[10] = 2.890611442640554f * xy * dz;
    rin[11] = 0.4570457994644657f * dy * (1.0f - 5.0f * z2);
    rin[12] = 0.3731763325901154f * dz * (5.0f * z2 - 3.0f);
    rin[13] = 0.4570457994644657f * dx * (1.0f - 5.0f * z2);
    rin[14] = 1.445305721320277f * dz * (x2 - y2);
    rin[15] = 0.5900435899266435f * dx * (-x2 + 3.0f * y2);
    #pragma unroll
    for (int k = 0; k < 16; k++) rin[16 + k] = g[1 + k];

    // ------------------------------------------------------------------
    // RGB MLP: 32 -> 64 (relu) -> 64 (relu) -> 3, sigmoid
    // ------------------------------------------------------------------
    #pragma unroll
    for (int j = 0; j < 64; j++) h[j] = 0.0f;
    #pragma unroll
    for (int i = 0; i < 32; i++) {
        float e = rin[i];
        const float4* w4 = reinterpret_cast<const float4*>(s_wr1 + i * 64);
        #pragma unroll
        for (int j4 = 0; j4 < 16; j4++) {
            float4 w = w4[j4];
            h[4 * j4 + 0] = fmaf(e, w.x, h[4 * j4 + 0]);
            h[4 * j4 + 1] = fmaf(e, w.y, h[4 * j4 + 1]);
            h[4 * j4 + 2] = fmaf(e, w.z, h[4 * j4 + 2]);
            h[4 * j4 + 3] = fmaf(e, w.w, h[4 * j4 + 3]);
        }
    }
    #pragma unroll
    for (int j = 0; j < 64; j++) h[j] = fmaxf(h[j], 0.0f);

    float h2[64];
    #pragma unroll
    for (int j = 0; j < 64; j++) h2[j] = 0.0f;
    #pragma unroll
    for (int i = 0; i < 64; i++) {
        float e = h[i];
        const float4* w4 = reinterpret_cast<const float4*>(s_wr2 + i * 64);
        #pragma unroll
        for (int j4 = 0; j4 < 16; j4++) {
            float4 w = w4[j4];
            h2[4 * j4 + 0] = fmaf(e, w.x, h2[4 * j4 + 0]);
            h2[4 * j4 + 1] = fmaf(e, w.y, h2[4 * j4 + 1]);
            h2[4 * j4 + 2] = fmaf(e, w.z, h2[4 * j4 + 2]);
            h2[4 * j4 + 3] = fmaf(e, w.w, h2[4 * j4 + 3]);
        }
    }
    #pragma unroll
    for (int j = 0; j < 64; j++) h2[j] = fmaxf(h2[j], 0.0f);

    #pragma unroll
    for (int c = 0; c < 3; c++) {
        const float4* w4 = reinterpret_cast<const float4*>(s_wr3t + c * 64);
        float acc = 0.0f;
        #pragma unroll
        for (int i4 = 0; i4 < 16; i4++) {
            float4 w = w4[i4];
            acc = fmaf(h2[4 * i4 + 0], w.x, acc);
            acc = fmaf(h2[4 * i4 + 1], w.y, acc);
            acc = fmaf(h2[4 * i4 + 2], w.z, acc);
            acc = fmaf(h2[4 * i4 + 3], w.w, acc);
        }
        out[3 * p + c] = 1.0f / (1.0f + expf(-acc));
    }
}

extern "C" void kernel_launch(void* const* d_in, const int* in_sizes, int n_in,
                              void* d_out, int out_size)
{
    const float* xyz = (const float*)d_in[0];
    const float* dir = (const float*)d_in[1];
    const float* table = (const float*)d_in[2];
    const float* ws1 = (const float*)d_in[3];
    const float* ws2 = (const float*)d_in[4];
    const float* wr1 = (const float*)d_in[5];
    const float* wr2 = (const float*)d_in[6];
    const float* wr3 = (const float*)d_in[7];
    float* out = (float*)d_out;

    int N = in_sizes[0] / 3;
    int blocks = (N + NTHREADS - 1) / NTHREADS;
    nerf_fused_kernel<<<blocks, NTHREADS>>>(xyz, dir, table, ws1, ws2,
                                            wr1, wr2, wr3, out, N);
}

// round 4
// speedup vs baseline: 1.0505x; 1.0505x over previous
#include <cuda_runtime.h>
#include <math.h>

#define NTHREADS 128

// All MLP weights in constant memory: warp-uniform reads go through the
// LDCU / uniform-register port (floor 1 cyc, separate from L1tex) instead of
// broadcast LDS through the overloaded L1 pipe.
__constant__ float c_ws1[32 * 64];   // [32][64] row-major
__constant__ float c_ws2[64 * 17];   // [64][17] row-major
__constant__ float c_wr1[32 * 64];   // [32][64]
__constant__ float c_wr2[64 * 64];   // [64][64]
__constant__ float c_wr3[64 * 3];    // [64][3]

__global__ __launch_bounds__(NTHREADS, 3)
void nerf_fused_kernel(const float* __restrict__ xyz,
                       const float* __restrict__ dirp,
                       const float* __restrict__ table,
                       float* __restrict__ out, int N)
{
    int p = blockIdx.x * NTHREADS + threadIdx.x;
    if (p >= N) return;

    float x = xyz[3 * p + 0];
    float y = xyz[3 * p + 1];
    float z = xyz[3 * p + 2];

    // ------------------------------------------------------------------
    // Hash-grid encoding: 16 levels, F=2 features, trilinear interp
    // ------------------------------------------------------------------
    float enc[32];
    const int res_tab[16] = {16, 22, 30, 42, 58, 80, 111, 153,
                             212, 294, 406, 561, 775, 1072, 1481, 2047};

    #pragma unroll
    for (int l = 0; l < 16; l++) {
        const int res = res_tab[l];
        float px = x * (float)res, py = y * (float)res, pz = z * (float)res;
        float fx = floorf(px), fy = floorf(py), fz = floorf(pz);
        float wx = px - fx, wy = py - fy, wz = pz - fz;
        unsigned ix = (unsigned)fx, iy = (unsigned)fy, iz = (unsigned)fz;

        unsigned i0, i1, i2, i3, i4, i5, i6, i7;
        if (res <= 79) {  // dense level: (res+1)^3 <= 2^19
            unsigned s = (unsigned)(res + 1);
            unsigned ss = s * s;
            unsigned base = ix + iy * s + iz * ss;
            i0 = base;      i1 = base + 1;
            i2 = base + s;  i3 = base + s + 1;
            i4 = base + ss; i5 = i4 + 1;
            i6 = i4 + s;    i7 = i4 + s + 1;
        } else {            // hashed level
            const unsigned P1 = 2654435761u, P2 = 805459861u;
            const unsigned m = (1u << 19) - 1u;
            unsigned hx0 = ix, hx1 = ix + 1u;
            unsigned hy0 = iy * P1, hy1 = hy0 + P1;
            unsigned hz0 = iz * P2, hz1 = hz0 + P2;
            i0 = (hx0 ^ hy0 ^ hz0) & m; i1 = (hx1 ^ hy0 ^ hz0) & m;
            i2 = (hx0 ^ hy1 ^ hz0) & m; i3 = (hx1 ^ hy1 ^ hz0) & m;
            i4 = (hx0 ^ hy0 ^ hz1) & m; i5 = (hx1 ^ hy0 ^ hz1) & m;
            i6 = (hx0 ^ hy1 ^ hz1) & m; i7 = (hx1 ^ hy1 ^ hz1) & m;
        }

        const float2* tl = reinterpret_cast<const float2*>(table) + ((size_t)l << 19);
        float2 f0 = __ldg(tl + i0); float2 f1 = __ldg(tl + i1);
        float2 f2 = __ldg(tl + i2); float2 f3 = __ldg(tl + i3);
        float2 f4 = __ldg(tl + i4); float2 f5 = __ldg(tl + i5);
        float2 f6 = __ldg(tl + i6); float2 f7 = __ldg(tl + i7);

        // lerp chain (x, then y, then z)
        float a0 = f0.x + wx * (f1.x - f0.x), b0 = f0.y + wx * (f1.y - f0.y);
        float a1 = f2.x + wx * (f3.x - f2.x), b1 = f2.y + wx * (f3.y - f2.y);
        float a2 = f4.x + wx * (f5.x - f4.x), b2 = f4.y + wx * (f5.y - f4.y);
        float a3 = f6.x + wx * (f7.x - f6.x), b3 = f6.y + wx * (f7.y - f6.y);
        float c0 = a0 + wy * (a1 - a0), d0 = b0 + wy * (b1 - b0);
        float c1 = a2 + wy * (a3 - a2), d1 = b2 + wy * (b3 - b2);
        enc[2 * l + 0] = c0 + wz * (c1 - c0);
        enc[2 * l + 1] = d0 + wz * (d1 - d0);
    }

    // ------------------------------------------------------------------
    // Sigma MLP: 32 -> 64 (relu) -> 17   (weights from constant/uniform port)
    // ------------------------------------------------------------------
    float h[64];
    #pragma unroll
    for (int j = 0; j < 64; j++) h[j] = 0.0f;
    #pragma unroll
    for (int i = 0; i < 32; i++) {
        float e = enc[i];
        #pragma unroll
        for (int j = 0; j < 64; j++)
            h[j] = fmaf(e, c_ws1[i * 64 + j], h[j]);
    }
    #pragma unroll
    for (int j = 0; j < 64; j++) h[j] = fmaxf(h[j], 0.0f);

    float g[17];
    #pragma unroll
    for (int j = 0; j < 17; j++) g[j] = 0.0f;
    #pragma unroll
    for (int i = 0; i < 64; i++) {
        float hi = h[i];
        #pragma unroll
        for (int j = 0; j < 17; j++)
            g[j] = fmaf(hi, c_ws2[i * 17 + j], g[j]);
    }

    // sigma output (relu), stored at [3N, 4N)
    out[3 * N + p] = fmaxf(g[0], 0.0f);

    // ------------------------------------------------------------------
    // SH degree-4 direction encoding on d = dir*2 - 1
    // ------------------------------------------------------------------
    float dx = dirp[3 * p + 0] * 2.0f - 1.0f;
    float dy = dirp[3 * p + 1] * 2.0f - 1.0f;
    float dz = dirp[3 * p + 2] * 2.0f - 1.0f;
    float x2 = dx * dx, y2 = dy * dy, z2 = dz * dz;
    float xy = dx * dy, yz = dy * dz, xz = dx * dz;

    float rin[32];
    rin[0]  = 0.28209479177387814f;
    rin[1]  = -0.48860251190291987f * dy;
    rin[2]  = 0.48860251190291987f * dz;
    rin[3]  = -0.48860251190291987f * dx;
    rin[4]  = 1.0925484305920792f * xy;
    rin[5]  = -1.0925484305920792f * yz;
    rin[6]  = 0.94617469575756f * z2 - 0.31539156525252f;
    rin[7]  = -1.0925484305920792f * xz;
    rin[8]  = 0.5462742152960396f * (x2 - y2);
    rin[9]  = 0.5900435899266435f * dy * (-3.0f * x2 + y2);
    rin[10] = 2.890611442640554f * xy * dz;
    rin[11] = 0.4570457994644657f * dy * (1.0f - 5.0f * z2);
    rin[12] = 0.3731763325901154f * dz * (5.0f * z2 - 3.0f);
    rin[13] = 0.4570457994644657f * dx * (1.0f - 5.0f * z2);
    rin[14] = 1.445305721320277f * dz * (x2 - y2);
    rin[15] = 0.5900435899266435f * dx * (-x2 + 3.0f * y2);
    #pragma unroll
    for (int k = 0; k < 16; k++) rin[16 + k] = g[1 + k];

    // ------------------------------------------------------------------
    // RGB MLP: 32 -> 64 (relu) -> 64 (relu) -> 3, sigmoid
    // ------------------------------------------------------------------
    #pragma unroll
    for (int j = 0; j < 64; j++) h[j] = 0.0f;
    #pragma unroll
    for (int i = 0; i < 32; i++) {
        float e = rin[i];
        #pragma unroll
        for (int j = 0; j < 64; j++)
            h[j] = fmaf(e, c_wr1[i * 64 + j], h[j]);
    }
    #pragma unroll
    for (int j = 0; j < 64; j++) h[j] = fmaxf(h[j], 0.0f);

    float h2[64];
    #pragma unroll
    for (int j = 0; j < 64; j++) h2[j] = 0.0f;
    #pragma unroll
    for (int i = 0; i < 64; i++) {
        float e = h[i];
        #pragma unroll
        for (int j = 0; j < 64; j++)
            h2[j] = fmaf(e, c_wr2[i * 64 + j], h2[j]);
    }
    #pragma unroll
    for (int j = 0; j < 64; j++) h2[j] = fmaxf(h2[j], 0.0f);

    float acc0 = 0.0f, acc1 = 0.0f, acc2 = 0.0f;
    #pragma unroll
    for (int i = 0; i < 64; i++) {
        float e = h2[i];
        acc0 = fmaf(e, c_wr3[i * 3 + 0], acc0);
        acc1 = fmaf(e, c_wr3[i * 3 + 1], acc1);
        acc2 = fmaf(e, c_wr3[i * 3 + 2], acc2);
    }
    out[3 * p + 0] = 1.0f / (1.0f + __expf(-acc0));
    out[3 * p + 1] = 1.0f / (1.0f + __expf(-acc1));
    out[3 * p + 2] = 1.0f / (1.0f + __expf(-acc2));
}

extern "C" void kernel_launch(void* const* d_in, const int* in_sizes, int n_in,
                              void* d_out, int out_size)
{
    const float* xyz = (const float*)d_in[0];
    const float* dir = (const float*)d_in[1];
    const float* table = (const float*)d_in[2];

    // Stage weights into constant memory (device-to-device async memcpy:
    // graph-capturable memcpy nodes, no allocation).
    cudaMemcpyToSymbolAsync(c_ws1, d_in[3], 32 * 64 * sizeof(float), 0,
                            cudaMemcpyDeviceToDevice, 0);
    cudaMemcpyToSymbolAsync(c_ws2, d_in[4], 64 * 17 * sizeof(float), 0,
                            cudaMemcpyDeviceToDevice, 0);
    cudaMemcpyToSymbolAsync(c_wr1, d_in[5], 32 * 64 * sizeof(float), 0,
                            cudaMemcpyDeviceToDevice, 0);
    cudaMemcpyToSymbolAsync(c_wr2, d_in[6], 64 * 64 * sizeof(float), 0,
                            cudaMemcpyDeviceToDevice, 0);
    cudaMemcpyToSymbolAsync(c_wr3, d_in[7], 64 * 3 * sizeof(float), 0,
                            cudaMemcpyDeviceToDevice, 0);

    float* out = (float*)d_out;
    int N = in_sizes[0] / 3;
    int blocks = (N + NTHREADS - 1) / NTHREADS;
    nerf_fused_kernel<<<blocks, NTHREADS>>>(xyz, dir, table, out, N);
}

// round 7
// speedup vs baseline: 1.1539x; 1.0984x over previous
#include <cuda_runtime.h>
#include <math.h>

#define NTHREADS 128
typedef unsigned long long u64;

__constant__ float c_ws1[32 * 64];   // [32][64] row-major
__constant__ float c_ws2[64 * 17];   // [64][17] row-major
__constant__ float c_wr1[32 * 64];   // [32][64]
__constant__ float c_wr2[64 * 64];   // [64][64]
__constant__ float c_wr3[64 * 3];    // [64][3]

// ---- packed f32x2 helpers (Blackwell FFMA2 path, PTX-only) ----
__device__ __forceinline__ u64 pack2(float lo, float hi) {
    u64 r; asm("mov.b64 %0,{%1,%2};" : "=l"(r) : "f"(lo), "f"(hi)); return r;
}
__device__ __forceinline__ void unpack2(u64 v, float& lo, float& hi) {
    asm("mov.b64 {%0,%1},%2;" : "=f"(lo), "=f"(hi) : "l"(v));
}
__device__ __forceinline__ u64 fma2(u64 a, u64 b, u64 c) {
    u64 d; asm("fma.rn.f32x2 %0,%1,%2,%3;" : "=l"(d) : "l"(a), "l"(b), "l"(c));
    return d;
}
__device__ __forceinline__ u64 mul2(u64 a, u64 b) {
    u64 d; asm("mul.rn.f32x2 %0,%1,%2;" : "=l"(d) : "l"(a), "l"(b));
    return d;
}

__global__ __launch_bounds__(NTHREADS, 3)
void nerf_fused_kernel(const float* __restrict__ xyz,
                       const float* __restrict__ dirp,
                       const float* __restrict__ table,
                       float* __restrict__ out, int N)
{
    int p = blockIdx.x * NTHREADS + threadIdx.x;
    if (p >= N) return;

    float x = xyz[3 * p + 0];
    float y = xyz[3 * p + 1];
    float z = xyz[3 * p + 2];

    // ------------------------------------------------------------------
    // Hash-grid encoding: 16 levels, F=2, trilinear interp (f32x2 lerps)
    // ------------------------------------------------------------------
    float enc[32];
    const int res_tab[16] = {16, 22, 30, 42, 58, 80, 111, 153,
                             212, 294, 406, 561, 775, 1072, 1481, 2047};

    #pragma unroll
    for (int l = 0; l < 16; l++) {
        const int res = res_tab[l];
        float px = x * (float)res, py = y * (float)res, pz = z * (float)res;
        float fx = floorf(px), fy = floorf(py), fz = floorf(pz);
        float wx = px - fx, wy = py - fy, wz = pz - fz;
        unsigned ix = (unsigned)fx, iy = (unsigned)fy, iz = (unsigned)fz;

        unsigned i0, i1, i2, i3, i4, i5, i6, i7;
        if (res <= 79) {  // dense level: (res+1)^3 <= 2^19
            unsigned s = (unsigned)(res + 1);
            unsigned ss = s * s;
            unsigned base = ix + iy * s + iz * ss;
            i0 = base;      i1 = base + 1;
            i2 = base + s;  i3 = base + s + 1;
            i4 = base + ss; i5 = i4 + 1;
            i6 = i4 + s;    i7 = i4 + s + 1;
        } else {            // hashed level
            const unsigned P1 = 2654435761u, P2 = 805459861u;
            const unsigned m = (1u << 19) - 1u;
            unsigned hx0 = ix, hx1 = ix + 1u;
            unsigned hy0 = iy * P1, hy1 = hy0 + P1;
            unsigned hz0 = iz * P2, hz1 = hz0 + P2;
            i0 = (hx0 ^ hy0 ^ hz0) & m; i1 = (hx1 ^ hy0 ^ hz0) & m;
            i2 = (hx0 ^ hy1 ^ hz0) & m; i3 = (hx1 ^ hy1 ^ hz0) & m;
            i4 = (hx0 ^ hy0 ^ hz1) & m; i5 = (hx1 ^ hy0 ^ hz1) & m;
            i6 = (hx0 ^ hy1 ^ hz1) & m; i7 = (hx1 ^ hy1 ^ hz1) & m;
        }

        const u64* tl = reinterpret_cast<const u64*>(table) + ((size_t)l << 19);
        u64 f0 = __ldg(tl + i0); u64 f1 = __ldg(tl + i1);
        u64 f2 = __ldg(tl + i2); u64 f3 = __ldg(tl + i3);
        u64 f4 = __ldg(tl + i4); u64 f5 = __ldg(tl + i5);
        u64 f6 = __ldg(tl + i6); u64 f7 = __ldg(tl + i7);

        float ox = 1.0f - wx, oy = 1.0f - wy, oz = 1.0f - wz;
        u64 wxp = pack2(wx, wx), oxp = pack2(ox, ox);
        u64 wyp = pack2(wy, wy), oyp = pack2(oy, oy);
        u64 wzp = pack2(wz, wz), ozp = pack2(oz, oz);

        u64 a0 = fma2(f1, wxp, mul2(f0, oxp));
        u64 a1 = fma2(f3, wxp, mul2(f2, oxp));
        u64 a2 = fma2(f5, wxp, mul2(f4, oxp));
        u64 a3 = fma2(f7, wxp, mul2(f6, oxp));
        u64 c0 = fma2(a1, wyp, mul2(a0, oyp));
        u64 c1 = fma2(a3, wyp, mul2(a2, oyp));
        u64 e  = fma2(c1, wzp, mul2(c0, ozp));
        unpack2(e, enc[2 * l + 0], enc[2 * l + 1]);
    }

    // ------------------------------------------------------------------
    // Sigma MLP: 32 -> 64 (relu) -> 17  (f32x2 first layer)
    // ------------------------------------------------------------------
    u64 hp[32];
    #pragma unroll
    for (int j = 0; j < 32; j++) hp[j] = 0ULL;
    #pragma unroll
    for (int i = 0; i < 32; i++) {
        u64 e2 = pack2(enc[i], enc[i]);
        const ulonglong2* wrow =
            reinterpret_cast<const ulonglong2*>(c_ws1 + i * 64);
        #pragma unroll
        for (int j = 0; j < 16; j++) {
            ulonglong2 w = wrow[j];
            hp[2 * j + 0] = fma2(e2, w.x, hp[2 * j + 0]);
            hp[2 * j + 1] = fma2(e2, w.y, hp[2 * j + 1]);
        }
    }
    float h[64];
    #pragma unroll
    for (int j = 0; j < 32; j++) {
        float lo, hi; unpack2(hp[j], lo, hi);
        h[2 * j + 0] = fmaxf(lo, 0.0f);
        h[2 * j + 1] = fmaxf(hi, 0.0f);
    }

    float g[17];
    #pragma unroll
    for (int j = 0; j < 17; j++) g[j] = 0.0f;
    #pragma unroll
    for (int i = 0; i < 64; i++) {
        float hi = h[i];
        #pragma unroll
        for (int j = 0; j < 17; j++)
            g[j] = fmaf(hi, c_ws2[i * 17 + j], g[j]);
    }

    out[3 * N + p] = fmaxf(g[0], 0.0f);   // sigma at [3N, 4N)

    // ------------------------------------------------------------------
    // SH degree-4 direction encoding on d = dir*2 - 1
    // ------------------------------------------------------------------
    float dx = dirp[3 * p + 0] * 2.0f - 1.0f;
    float dy = dirp[3 * p + 1] * 2.0f - 1.0f;
    float dz = dirp[3 * p + 2] * 2.0f - 1.0f;
    float x2 = dx * dx, y2 = dy * dy, z2 = dz * dz;
    float xy = dx * dy, yz = dy * dz, xz = dx * dz;

    float rin[32];
    rin[0]  = 0.28209479177387814f;
    rin[1]  = -0.48860251190291987f * dy;
    rin[2]  = 0.48860251190291987f * dz;
    rin[3]  = -0.48860251190291987f * dx;
    rin[4]  = 1.0925484305920792f * xy;
    rin[5]  = -1.0925484305920792f * yz;
    rin[6]  = 0.94617469575756f * z2 - 0.31539156525252f;
    rin[7]  = -1.0925484305920792f * xz;
    rin[8]  = 0.5462742152960396f * (x2 - y2);
    rin[9]  = 0.5900435899266435f * dy * (-3.0f * x2 + y2);
    rin[10] = 2.890611442640554f * xy * dz;
    rin[11] = 0.4570457994644657f * dy * (1.0f - 5.0f * z2);
    rin[12] = 0.3731763325901154f * dz * (5.0f * z2 - 3.0f);
    rin[13] = 0.4570457994644657f * dx * (1.0f - 5.0f * z2);
    rin[14] = 1.445305721320277f * dz * (x2 - y2);
    rin[15] = 0.5900435899266435f * dx * (-x2 + 3.0f * y2);
    #pragma unroll
    for (int k = 0; k < 16; k++) rin[16 + k] = g[1 + k];

    // ------------------------------------------------------------------
    // RGB MLP: 32 -> 64 (relu) -> 64 (relu) -> 3, sigmoid  (f32x2)
    // ------------------------------------------------------------------
    #pragma unroll
    for (int j = 0; j < 32; j++) hp[j] = 0ULL;
    #pragma unroll
    for (int i = 0; i < 32; i++) {
        u64 e2 = pack2(rin[i], rin[i]);
        const ulonglong2* wrow =
            reinterpret_cast<const ulonglong2*>(c_wr1 + i * 64);
        #pragma unroll
        for (int j = 0; j < 16; j++) {
            ulonglong2 w = wrow[j];
            hp[2 * j + 0] = fma2(e2, w.x, hp[2 * j + 0]);
            hp[2 * j + 1] = fma2(e2, w.y, hp[2 * j + 1]);
        }
    }
    #pragma unroll
    for (int j = 0; j < 32; j++) {
        float lo, hi; unpack2(hp[j], lo, hi);
        h[2 * j + 0] = fmaxf(lo, 0.0f);
        h[2 * j + 1] = fmaxf(hi, 0.0f);
    }

    u64 hp2[32];
    #pragma unroll
    for (int j = 0; j < 32; j++) hp2[j] = 0ULL;
    #pragma unroll
    for (int i = 0; i < 64; i++) {
        u64 e2 = pack2(h[i], h[i]);
        const ulonglong2* wrow =
            reinterpret_cast<const ulonglong2*>(c_wr2 + i * 64);
        #pragma unroll
        for (int j = 0; j < 16; j++) {
            ulonglong2 w = wrow[j];
            hp2[2 * j + 0] = fma2(e2, w.x, hp2[2 * j + 0]);
            hp2[2 * j + 1] = fma2(e2, w.y, hp2[2 * j + 1]);
        }
    }
    float h2[64];
    #pragma unroll
    for (int j = 0; j < 32; j++) {
        float lo, hi; unpack2(hp2[j], lo, hi);
        h2[2 * j + 0] = fmaxf(lo, 0.0f);
        h2[2 * j + 1] = fmaxf(hi, 0.0f);
    }

    float acc0 = 0.0f, acc1 = 0.0f, acc2 = 0.0f;
    #pragma unroll
    for (int i = 0; i < 64; i++) {
        float e = h2[i];
        acc0 = fmaf(e, c_wr3[i * 3 + 0], acc0);
        acc1 = fmaf(e, c_wr3[i * 3 + 1], acc1);
        acc2 = fmaf(e, c_wr3[i * 3 + 2], acc2);
    }
    out[3 * p + 0] = 1.0f / (1.0f + __expf(-acc0));
    out[3 * p + 1] = 1.0f / (1.0f + __expf(-acc1));
    out[3 * p + 2] = 1.0f / (1.0f + __expf(-acc2));
}

extern "C" void kernel_launch(void* const* d_in, const int* in_sizes, int n_in,
                              void* d_out, int out_size)
{
    const float* xyz = (const float*)d_in[0];
    const float* dir = (const float*)d_in[1];
    const float* table = (const float*)d_in[2];

    cudaMemcpyToSymbolAsync(c_ws1, d_in[3], 32 * 64 * sizeof(float), 0,
                            cudaMemcpyDeviceToDevice, 0);
    cudaMemcpyToSymbolAsync(c_ws2, d_in[4], 64 * 17 * sizeof(float), 0,
                            cudaMemcpyDeviceToDevice, 0);
    cudaMemcpyToSymbolAsync(c_wr1, d_in[5], 32 * 64 * sizeof(float), 0,
                            cudaMemcpyDeviceToDevice, 0);
    cudaMemcpyToSymbolAsync(c_wr2, d_in[6], 64 * 64 * sizeof(float), 0,
                            cudaMemcpyDeviceToDevice, 0);
    cudaMemcpyToSymbolAsync(c_wr3, d_in[7], 64 * 3 * sizeof(float), 0,
                            cudaMemcpyDeviceToDevice, 0);

    float* out = (float*)d_out;
    int N = in_sizes[0] / 3;
    int blocks = (N + NTHREADS - 1) / NTHREADS;
    nerf_fused_kernel<<<blocks, NTHREADS>>>(xyz, dir, table, out, N);
}

// round 9
// speedup vs baseline: 1.2191x; 1.0565x over previous
#include <cuda_runtime.h>
#include <math.h>

#define NTHREADS 128
typedef unsigned long long u64;

// Only ws1 stays in constant memory (balancing the LDC port vs L1tex/smem).
__constant__ float c_ws1[32 * 64];   // [32][64] row-major

// ---- packed f32x2 helpers (Blackwell FFMA2 path, PTX-only) ----
__device__ __forceinline__ u64 pack2(float lo, float hi) {
    u64 r; asm("mov.b64 %0,{%1,%2};" : "=l"(r) : "f"(lo), "f"(hi)); return r;
}
__device__ __forceinline__ void unpack2(u64 v, float& lo, float& hi) {
    asm("mov.b64 {%0,%1},%2;" : "=f"(lo), "=f"(hi) : "l"(v));
}
__device__ __forceinline__ u64 fma2(u64 a, u64 b, u64 c) {
    u64 d; asm("fma.rn.f32x2 %0,%1,%2,%3;" : "=l"(d) : "l"(a), "l"(b), "l"(c));
    return d;
}
__device__ __forceinline__ u64 mul2(u64 a, u64 b) {
    u64 d; asm("mul.rn.f32x2 %0,%1,%2;" : "=l"(d) : "l"(a), "l"(b));
    return d;
}
__device__ __forceinline__ u64 relu2(u64 v) {
    float lo, hi; unpack2(v, lo, hi);
    return pack2(fmaxf(lo, 0.0f), fmaxf(hi, 0.0f));
}

__global__ __launch_bounds__(NTHREADS, 4)
void nerf_fused_kernel(const float* __restrict__ xyz,
                       const float* __restrict__ dirp,
                       const float* __restrict__ table,
                       const float* __restrict__ ws2g,
                       const float* __restrict__ wr1g,
                       const float* __restrict__ wr2g,
                       const float* __restrict__ wr3g,
                       float* __restrict__ out, int N)
{
    // Shared weights (LDS.128 broadcast path; floor 2 vs LDC floor 8)
    __shared__ __align__(16) float s_wr1[32 * 64];    //  8 KB row-major
    __shared__ __align__(16) float s_wr2[64 * 64];    // 16 KB row-major
    __shared__ __align__(16) float s_ws2t[17 * 64];   // transposed [j][i]
    __shared__ __align__(16) float s_wr3t[3 * 64];    // transposed [c][i]

    {
        const float4* src1 = reinterpret_cast<const float4*>(wr1g);
        float4* dst1 = reinterpret_cast<float4*>(s_wr1);
        for (int t = threadIdx.x; t < 512; t += NTHREADS) dst1[t] = src1[t];
        const float4* src2 = reinterpret_cast<const float4*>(wr2g);
        float4* dst2 = reinterpret_cast<float4*>(s_wr2);
        for (int t = threadIdx.x; t < 1024; t += NTHREADS) dst2[t] = src2[t];
        for (int t = threadIdx.x; t < 17 * 64; t += NTHREADS) {
            int j = t >> 6, i = t & 63;
            s_ws2t[t] = ws2g[i * 17 + j];
        }
        for (int t = threadIdx.x; t < 3 * 64; t += NTHREADS) {
            int c = t >> 6, i = t & 63;
            s_wr3t[t] = wr3g[i * 3 + c];
        }
    }
    __syncthreads();

    int p = blockIdx.x * NTHREADS + threadIdx.x;
    if (p >= N) return;

    float x = xyz[3 * p + 0];
    float y = xyz[3 * p + 1];
    float z = xyz[3 * p + 2];

    // ------------------------------------------------------------------
    // Hash-grid encoding: 16 levels, F=2, trilinear interp (f32x2 lerps)
    // ------------------------------------------------------------------
    float enc[32];
    const int res_tab[16] = {16, 22, 30, 42, 58, 80, 111, 153,
                             212, 294, 406, 561, 775, 1072, 1481, 2047};

    #pragma unroll
    for (int l = 0; l < 16; l++) {
        const int res = res_tab[l];
        float px = x * (float)res, py = y * (float)res, pz = z * (float)res;
        float fx = floorf(px), fy = floorf(py), fz = floorf(pz);
        float wx = px - fx, wy = py - fy, wz = pz - fz;
        unsigned ix = (unsigned)fx, iy = (unsigned)fy, iz = (unsigned)fz;

        unsigned i0, i1, i2, i3, i4, i5, i6, i7;
        if (res <= 79) {  // dense level: (res+1)^3 <= 2^19
            unsigned s = (unsigned)(res + 1);
            unsigned ss = s * s;
            unsigned base = ix + iy * s + iz * ss;
            i0 = base;      i1 = base + 1;
            i2 = base + s;  i3 = base + s + 1;
            i4 = base + ss; i5 = i4 + 1;
            i6 = i4 + s;    i7 = i4 + s + 1;
        } else {            // hashed level
            const unsigned P1 = 2654435761u, P2 = 805459861u;
            const unsigned m = (1u << 19) - 1u;
            unsigned hx0 = ix, hx1 = ix + 1u;
            unsigned hy0 = iy * P1, hy1 = hy0 + P1;
            unsigned hz0 = iz * P2, hz1 = hz0 + P2;
            i0 = (hx0 ^ hy0 ^ hz0) & m; i1 = (hx1 ^ hy0 ^ hz0) & m;
            i2 = (hx0 ^ hy1 ^ hz0) & m; i3 = (hx1 ^ hy1 ^ hz0) & m;
            i4 = (hx0 ^ hy0 ^ hz1) & m; i5 = (hx1 ^ hy0 ^ hz1) & m;
            i6 = (hx0 ^ hy1 ^ hz1) & m; i7 = (hx1 ^ hy1 ^ hz1) & m;
        }

        const u64* tl = reinterpret_cast<const u64*>(table) + ((size_t)l << 19);
        u64 f0 = __ldg(tl + i0); u64 f1 = __ldg(tl + i1);
        u64 f2 = __ldg(tl + i2); u64 f3 = __ldg(tl + i3);
        u64 f4 = __ldg(tl + i4); u64 f5 = __ldg(tl + i5);
        u64 f6 = __ldg(tl + i6); u64 f7 = __ldg(tl + i7);

        float ox = 1.0f - wx, oy = 1.0f - wy, oz = 1.0f - wz;
        u64 wxp = pack2(wx, wx), oxp = pack2(ox, ox);
        u64 wyp = pack2(wy, wy), oyp = pack2(oy, oy);
        u64 wzp = pack2(wz, wz), ozp = pack2(oz, oz);

        u64 a0 = fma2(f1, wxp, mul2(f0, oxp));
        u64 a1 = fma2(f3, wxp, mul2(f2, oxp));
        u64 a2 = fma2(f5, wxp, mul2(f4, oxp));
        u64 a3 = fma2(f7, wxp, mul2(f6, oxp));
        u64 c0 = fma2(a1, wyp, mul2(a0, oyp));
        u64 c1 = fma2(a3, wyp, mul2(a2, oyp));
        u64 e  = fma2(c1, wzp, mul2(c0, ozp));
        unpack2(e, enc[2 * l + 0], enc[2 * l + 1]);
    }

    // ------------------------------------------------------------------
    // Sigma MLP layer 1: 32 -> 64 relu (ws1 from constant), packed pairs
    // ------------------------------------------------------------------
    u64 hp[32];
    #pragma unroll
    for (int j = 0; j < 32; j++) hp[j] = 0ULL;
    #pragma unroll
    for (int i = 0; i < 32; i++) {
        u64 e2 = pack2(enc[i], enc[i]);
        const ulonglong2* wrow =
            reinterpret_cast<const ulonglong2*>(c_ws1 + i * 64);
        #pragma unroll
        for (int j = 0; j < 16; j++) {
            ulonglong2 w = wrow[j];
            hp[2 * j + 0] = fma2(e2, w.x, hp[2 * j + 0]);
            hp[2 * j + 1] = fma2(e2, w.y, hp[2 * j + 1]);
        }
    }
    #pragma unroll
    for (int j = 0; j < 32; j++) hp[j] = relu2(hp[j]);

    // ------------------------------------------------------------------
    // Sigma MLP layer 2: 64 -> 17 (ws2 transposed in shared, packed over i)
    // ------------------------------------------------------------------
    float g[17];
    #pragma unroll
    for (int j = 0; j < 17; j++) {
        const ulonglong2* row =
            reinterpret_cast<const ulonglong2*>(s_ws2t + j * 64);
        u64 acc = 0ULL;
        #pragma unroll
        for (int m = 0; m < 16; m++) {
            ulonglong2 w = row[m];
            acc = fma2(hp[2 * m + 0], w.x, acc);
            acc = fma2(hp[2 * m + 1], w.y, acc);
        }
        float lo, hi; unpack2(acc, lo, hi);
        g[j] = lo + hi;
    }

    out[3 * N + p] = fmaxf(g[0], 0.0f);   // sigma at [3N, 4N)

    // ------------------------------------------------------------------
    // SH degree-4 direction encoding on d = dir*2 - 1
    // ------------------------------------------------------------------
    float dx = dirp[3 * p + 0] * 2.0f - 1.0f;
    float dy = dirp[3 * p + 1] * 2.0f - 1.0f;
    float dz = dirp[3 * p + 2] * 2.0f - 1.0f;
    float x2 = dx * dx, y2 = dy * dy, z2 = dz * dz;
    float xy = dx * dy, yz = dy * dz, xz = dx * dz;

    float rin[32];
    rin[0]  = 0.28209479177387814f;
    rin[1]  = -0.48860251190291987f * dy;
    rin[2]  = 0.48860251190291987f * dz;
    rin[3]  = -0.48860251190291987f * dx;
    rin[4]  = 1.0925484305920792f * xy;
    rin[5]  = -1.0925484305920792f * yz;
    rin[6]  = 0.94617469575756f * z2 - 0.31539156525252f;
    rin[7]  = -1.0925484305920792f * xz;
    rin[8]  = 0.5462742152960396f * (x2 - y2);
    rin[9]  = 0.5900435899266435f * dy * (-3.0f * x2 + y2);
    rin[10] = 2.890611442640554f * xy * dz;
    rin[11] = 0.4570457994644657f * dy * (1.0f - 5.0f * z2);
    rin[12] = 0.3731763325901154f * dz * (5.0f * z2 - 3.0f);
    rin[13] = 0.4570457994644657f * dx * (1.0f - 5.0f * z2);
    rin[14] = 1.445305721320277f * dz * (x2 - y2);
    rin[15] = 0.5900435899266435f * dx * (-x2 + 3.0f * y2);
    #pragma unroll
    for (int k = 0; k < 16; k++) rin[16 + k] = g[1 + k];

    // ------------------------------------------------------------------
    // RGB layer 1: 32 -> 64 relu (wr1 from shared), packed pairs
    // ------------------------------------------------------------------
    #pragma unroll
    for (int j = 0; j < 32; j++) hp[j] = 0ULL;
    #pragma unroll
    for (int i = 0; i < 32; i++) {
        u64 e2 = pack2(rin[i], rin[i]);
        const ulonglong2* wrow =
            reinterpret_cast<const ulonglong2*>(s_wr1 + i * 64);
        #pragma unroll
        for (int j = 0; j < 16; j++) {
            ulonglong2 w = wrow[j];
            hp[2 * j + 0] = fma2(e2, w.x, hp[2 * j + 0]);
            hp[2 * j + 1] = fma2(e2, w.y, hp[2 * j + 1]);
        }
    }
    #pragma unroll
    for (int j = 0; j < 32; j++) hp[j] = relu2(hp[j]);

    // ------------------------------------------------------------------
    // RGB layer 2 (64 -> 64 relu) in two 32-output halves, fused with
    // RGB layer 3 (64 -> 3) partial accumulation — caps live registers.
    // ------------------------------------------------------------------
    u64 racc0 = 0ULL, racc1 = 0ULL, racc2 = 0ULL;

    #pragma unroll
    for (int half = 0; half < 2; half++) {
        u64 acc[16];
        #pragma unroll
        for (int j = 0; j < 16; j++) acc[j] = 0ULL;

        #pragma unroll
        for (int i = 0; i < 64; i++) {
            float elo, ehi; unpack2(hp[i >> 1], elo, ehi);
            float e = (i & 1) ? ehi : elo;
            u64 e2 = pack2(e, e);
            const ulonglong2* wrow = reinterpret_cast<const ulonglong2*>(
                s_wr2 + i * 64 + half * 32);
            #pragma unroll
            for (int j = 0; j < 8; j++) {
                ulonglong2 w = wrow[j];
                acc[2 * j + 0] = fma2(e2, w.x, acc[2 * j + 0]);
                acc[2 * j + 1] = fma2(e2, w.y, acc[2 * j + 1]);
            }
        }
        #pragma unroll
        for (int j = 0; j < 16; j++) acc[j] = relu2(acc[j]);

        // layer-3 partials for this half (wr3 transposed, packed over i)
        const ulonglong2* r0 = reinterpret_cast<const ulonglong2*>(
            s_wr3t + 0 * 64 + half * 32);
        const ulonglong2* r1 = reinterpret_cast<const ulonglong2*>(
            s_wr3t + 1 * 64 + half * 32);
        const ulonglong2* r2 = reinterpret_cast<const ulonglong2*>(
            s_wr3t + 2 * 64 + half * 32);
        #pragma unroll
        for (int m = 0; m < 8; m++) {
            ulonglong2 w0 = r0[m], w1 = r1[m], w2 = r2[m];
            racc0 = fma2(acc[2 * m + 0], w0.x, racc0);
            racc0 = fma2(acc[2 * m + 1], w0.y, racc0);
            racc1 = fma2(acc[2 * m + 0], w1.x, racc1);
            racc1 = fma2(acc[2 * m + 1], w1.y, racc1);
            racc2 = fma2(acc[2 * m + 0], w2.x, racc2);
            racc2 = fma2(acc[2 * m + 1], w2.y, racc2);
        }
    }

    float l0, h0, l1, h1, l2, h2v;
    unpack2(racc0, l0, h0);
    unpack2(racc1, l1, h1);
    unpack2(racc2, l2, h2v);
    float a0 = l0 + h0, a1 = l1 + h1, a2 = l2 + h2v;
    out[3 * p + 0] = 1.0f / (1.0f + __expf(-a0));
    out[3 * p + 1] = 1.0f / (1.0f + __expf(-a1));
    out[3 * p + 2] = 1.0f / (1.0f + __expf(-a2));
}

extern "C" void kernel_launch(void* const* d_in, const int* in_sizes, int n_in,
                              void* d_out, int out_size)
{
    const float* xyz = (const float*)d_in[0];
    const float* dir = (const float*)d_in[1];
    const float* table = (const float*)d_in[2];

    cudaMemcpyToSymbolAsync(c_ws1, d_in[3], 32 * 64 * sizeof(float), 0,
                            cudaMemcpyDeviceToDevice, 0);

    float* out = (float*)d_out;
    int N = in_sizes[0] / 3;
    int blocks = (N + NTHREADS - 1) / NTHREADS;
    nerf_fused_kernel<<<blocks, NTHREADS>>>(xyz, dir, table,
                                            (const float*)d_in[4],
                                            (const float*)d_in[5],
                                            (const float*)d_in[6],
                                            (const float*)d_in[7],
                                            out, N);
}